// round 15
// baseline (speedup 1.0000x reference)
#include <cuda_runtime.h>
#include <cuda_fp16.h>
#include <cstdint>
#include <cstddef>

// ---------------------------------------------------------------------------
// out[8192,4096] = x[8192,4096] @ W^T + b,  W = mu + exp(log_sigma)*eps
// R15 = R14 resubmitted verbatim (R14 bench was an infra failure, not a
// kernel verdict). R12 GEMM consumer loop untouched; x->fp16 conversion
// folded into the A-side producers; prep handles only W sampling + bias.
// FULL barrier: 64 cp-arrivals (W) + 64 release-arrivals (A STS) = 128.
// ---------------------------------------------------------------------------
#define NROWS 8192
#define KDIM  4096
#define ODIM  4096

#define TILE_M 256
#define TILE_N 128
#define TILE_K 64                          // fp16: 64 halfs = 128 B/row
#define STAGES 4
#define K_ITERS (KDIM / TILE_K)            // 64

#define A_BYTES (TILE_M * TILE_K * 2)      // 32768
#define B_BYTES (TILE_N * TILE_K * 2)      // 16384
#define STAGE_BYTES (A_BYTES + B_BYTES)    // 49152
#define OFF_BAR   (STAGES * STAGE_BYTES)   // 196608
#define SMEM_TOTAL (OFF_BAR + 128)

__device__ __half g_W[(size_t)ODIM * KDIM];
__device__ float  g_B[ODIM];

// ---------------------------------------------------------------------------
__device__ __forceinline__ uint32_t smem_u32(const void* p) {
    uint32_t a;
    asm("{ .reg .u64 t; cvta.to.shared.u64 t, %1; cvt.u32.u64 %0, t; }"
        : "=r"(a) : "l"(p));
    return a;
}
__device__ __forceinline__ void cp16(uint32_t smem_dst, const void* gptr) {
    asm volatile("cp.async.cg.shared.global [%0], [%1], 16;"
                 :: "r"(smem_dst), "l"(gptr) : "memory");
}
__device__ __forceinline__ void cp_async_arrive(uint32_t mbar) {
    asm volatile("cp.async.mbarrier.arrive.noinc.shared.b64 [%0];"
                 :: "r"(mbar) : "memory");
}
#define MBARRIER_INIT(addr, cnt) \
    asm volatile("mbarrier.init.shared.b64 [%0], %1;" :: "r"(addr), "r"(cnt) : "memory")
#define MBARRIER_ARRIVE(addr) \
    asm volatile("mbarrier.arrive.shared.b64 _, [%0];" :: "r"(addr) : "memory")

__device__ __forceinline__ void mbar_wait(uint32_t mbar, uint32_t parity) {
    uint32_t done;
    asm volatile(
        "{ .reg .pred p; mbarrier.try_wait.parity.acquire.cta.shared::cta.b64 p, [%1], %2;"
        " selp.b32 %0, 1, 0, p; }"
        : "=r"(done) : "r"(mbar), "r"(parity) : "memory");
    if (!done) {
        asm volatile(
            "{ .reg .pred P1;\n"
            "WAIT_LOOP_%=:\n"
            " mbarrier.try_wait.parity.acquire.cta.shared::cta.b64 P1, [%0], %1, 0x989680;\n"
            " @P1 bra.uni WAIT_DONE_%=;\n"
            " bra.uni WAIT_LOOP_%=;\n"
            "WAIT_DONE_%=:\n}"
            :: "r"(mbar), "r"(parity) : "memory");
    }
}

__device__ __forceinline__ void ldsm_x4(uint32_t* r, uint32_t addr) {
    asm volatile("ldmatrix.sync.aligned.m8n8.x4.shared.b16 {%0,%1,%2,%3}, [%4];"
                 : "=r"(r[0]), "=r"(r[1]), "=r"(r[2]), "=r"(r[3]) : "r"(addr));
}
__device__ __forceinline__ void mma_f16(float* c, const uint32_t* a,
                                        uint32_t b0, uint32_t b1) {
    asm("mma.sync.aligned.m16n8k16.row.col.f32.f16.f16.f32 "
        "{%0,%1,%2,%3}, {%4,%5,%6,%7}, {%8,%9}, {%0,%1,%2,%3};"
        : "+f"(c[0]), "+f"(c[1]), "+f"(c[2]), "+f"(c[3])
        : "r"(a[0]), "r"(a[1]), "r"(a[2]), "r"(a[3]), "r"(b0), "r"(b1));
}

// Load one x row chunk (8 f32 = 32B), convert to 8 halfs, store 16B to smem.
__device__ __forceinline__ void ldcvt_sts(const float* g, uint32_t saddr) {
    const float4 u0 = __ldg((const float4*)g);
    const float4 u1 = __ldg((const float4*)g + 1);
    uint32_t q0, q1, q2, q3;
    asm("cvt.rn.f16x2.f32 %0, %1, %2;" : "=r"(q0) : "f"(u0.y), "f"(u0.x));
    asm("cvt.rn.f16x2.f32 %0, %1, %2;" : "=r"(q1) : "f"(u0.w), "f"(u0.z));
    asm("cvt.rn.f16x2.f32 %0, %1, %2;" : "=r"(q2) : "f"(u1.y), "f"(u1.x));
    asm("cvt.rn.f16x2.f32 %0, %1, %2;" : "=r"(q3) : "f"(u1.w), "f"(u1.z));
    asm volatile("st.shared.v4.b32 [%0], {%1,%2,%3,%4};"
                 :: "r"(saddr), "r"(q0), "r"(q1), "r"(q2), "r"(q3) : "memory");
}

// ---------------------------------------------------------------------------
// Prep: blocks [0, 8192) sample+convert W; block 8192 samples bias.
// ---------------------------------------------------------------------------
#define PREP_W_BLOCKS 8192
#define PREP_BLOCKS (PREP_W_BLOCKS + 1)

__global__ void prep_all_kernel(const float4* __restrict__ mu,
                                const float4* __restrict__ ls,
                                const float4* __restrict__ eps,
                                const float* __restrict__ mub,
                                const float* __restrict__ lsb,
                                const float* __restrict__ epsb) {
    const int b = blockIdx.x;
    if (b < PREP_W_BLOCKS) {
        size_t i = (size_t)b * blockDim.x + threadIdx.x;
        __half2 h[4];
        #pragma unroll
        for (int q = 0; q < 2; ++q) {
            float4 m = mu[2 * i + q], l = ls[2 * i + q], e = eps[2 * i + q];
            float4 w;
            w.x = m.x + expf(l.x) * e.x;
            w.y = m.y + expf(l.y) * e.y;
            w.z = m.z + expf(l.z) * e.z;
            w.w = m.w + expf(l.w) * e.w;
            h[2 * q + 0] = __floats2half2_rn(w.x, w.y);
            h[2 * q + 1] = __floats2half2_rn(w.z, w.w);
        }
        reinterpret_cast<uint4*>(g_W)[i] = *reinterpret_cast<uint4*>(h);
    } else {
        for (int i = threadIdx.x; i < ODIM; i += blockDim.x)
            g_B[i] = mub[i] + expf(lsb[i]) * epsb[i];
    }
}

// ---------------------------------------------------------------------------
// GEMM: 1024 CTAs (32 m x 32 n, n fastest), 320 threads:
// warps 0-7 consumers (64x64 in 4x2), warps 8-9 producers (A/B halves).
// A (x) loaded f32 + converted in producer; B (W) via cp.async.
// ---------------------------------------------------------------------------
__global__ void __launch_bounds__(320, 1)
rand_linear_gemm_kernel(const float* __restrict__ x, float* __restrict__ out) {
    extern __shared__ char smem[];
    const uint32_t sb = smem_u32(smem);
    const int tid = threadIdx.x;
    const int lane = tid & 31;
    const int wid = tid >> 5;

    const int m_tile = blockIdx.x >> 5;    // 32
    const int n_tile = blockIdx.x & 31;    // 32 (fast-varying: W stays L2-hot)
    const int m0 = m_tile * TILE_M;
    const int n0 = n_tile * TILE_N;

    #define FULL_BAR(s)  (sb + OFF_BAR + (s) * 16)
    #define EMPTY_BAR(s) (sb + OFF_BAR + (s) * 16 + 8)

    if (tid == 0) {
        #pragma unroll
        for (int s = 0; s < STAGES; ++s) {
            MBARRIER_INIT(FULL_BAR(s), 128u);   // 64 cp-arrives + 64 STS arrives
            MBARRIER_INIT(EMPTY_BAR(s), 256u);  // 8 consumer warps x 32 lanes
        }
    }
    __syncthreads();

    if (wid >= 8) {
        const int ph = wid - 8;            // 0 or 1
        const int r0 = lane >> 3;          // 0..3
        const int tc = lane & 7;           // 16B f16 chunk = 8 f32 of x
        const float*  gA = x + (size_t)(m0 + ph * 128 + r0) * KDIM + tc * 8;
        const __half* gB = g_W + (size_t)(n0 + ph * 64 + r0) * KDIM + tc * 8;
        const uint32_t aOff = (uint32_t)(ph * 128) * 128u;
        const uint32_t bOff = (uint32_t)(ph * 64) * 128u;
        const uint32_t sw0 = (uint32_t)r0 * 128u + (uint32_t)((tc ^ (r0 & 7)) << 4);
        const uint32_t sw1 = (uint32_t)(r0 + 4) * 128u +
                             (uint32_t)((tc ^ ((r0 + 4) & 7)) << 4);

        int slot = 0, phase = 1;
        for (int it = 0; it < K_ITERS; ++it) {
            mbar_wait(EMPTY_BAR(slot), phase);
            const uint32_t aS = sb + slot * STAGE_BYTES + aOff;
            const uint32_t bS = sb + slot * STAGE_BYTES + A_BYTES + bOff;
            const float*  ga = gA + it * TILE_K;
            const __half* gb = gB + it * TILE_K;
            #pragma unroll
            for (int j = 0; j < 16; ++j) {   // A half: 128 rows, f32->f16
                ldcvt_sts(ga + (size_t)(8 * j) * KDIM,     aS + sw0 + j * 1024u);
                ldcvt_sts(ga + (size_t)(8 * j + 4) * KDIM, aS + sw1 + j * 1024u);
            }
            #pragma unroll
            for (int j = 0; j < 8; ++j) {    // B half: 64 rows via cp.async
                cp16(bS + sw0 + j * 1024u, gb + (size_t)(8 * j) * KDIM);
                cp16(bS + sw1 + j * 1024u, gb + (size_t)(8 * j + 4) * KDIM);
            }
            cp_async_arrive(FULL_BAR(slot));   // completes when B copies land
            MBARRIER_ARRIVE(FULL_BAR(slot));   // release: orders A STS data
            if (++slot == STAGES) { slot = 0; phase ^= 1; }
        }
        return;
    }

    // --------------------------- consumer warps (R12 verbatim) -------------
    const int wm0 = (wid & 3) * 64;
    const int wn0 = (wid >> 2) * 64;

    const int la15 = lane & 15;
    const uint32_t hi = (uint32_t)(lane >> 4);
    uint32_t aRow[4], aX7[4], bRow[4], bX7[4];
    #pragma unroll
    for (int i = 0; i < 4; ++i) {
        const uint32_t ra = (uint32_t)(wm0 + i * 16 + la15);
        aRow[i] = ra * 128u; aX7[i] = ra & 7u;
        const uint32_t rb = (uint32_t)(wn0 + i * 16 + la15);
        bRow[i] = rb * 128u; bX7[i] = rb & 7u;
    }

    float acc[4][8][4];
    #pragma unroll
    for (int i = 0; i < 4; ++i)
        #pragma unroll
        for (int j = 0; j < 8; ++j)
            #pragma unroll
            for (int r = 0; r < 4; ++r) acc[i][j][r] = 0.f;

    uint32_t a[2][4][4], b[2][4][4];

    #define LOAD_FRAGS(kk, buf, aB_, bB_)                                     \
        do {                                                                  \
            const uint32_t kc2 = (uint32_t)((kk) * 2) + hi;                   \
            _Pragma("unroll")                                                 \
            for (int i_ = 0; i_ < 4; ++i_)                                    \
                ldsm_x4(a[buf][i_], (aB_) + aRow[i_] + ((kc2 ^ aX7[i_]) << 4)); \
            _Pragma("unroll")                                                 \
            for (int j_ = 0; j_ < 4; ++j_)                                    \
                ldsm_x4(b[buf][j_], (bB_) + bRow[j_] + ((kc2 ^ bX7[j_]) << 4)); \
        } while (0)

    #define MMA_BLOCK(buf)                                                    \
        do {                                                                  \
            _Pragma("unroll")                                                 \
            for (int i_ = 0; i_ < 4; ++i_) {                                  \
                _Pragma("unroll")                                             \
                for (int j_ = 0; j_ < 4; ++j_) {                              \
                    mma_f16(acc[i_][2 * j_ + 0], a[buf][i_], b[buf][j_][0],   \
                            b[buf][j_][2]);                                   \
                    mma_f16(acc[i_][2 * j_ + 1], a[buf][i_], b[buf][j_][1],   \
                            b[buf][j_][3]);                                   \
                }                                                             \
            }                                                                 \
        } while (0)

    int slot = 0, phase = 0;
    for (int it = 0; it < K_ITERS; ++it) {
        mbar_wait(FULL_BAR(slot), phase);
        const uint32_t aB = sb + slot * STAGE_BYTES;
        const uint32_t bB = aB + A_BYTES;

        LOAD_FRAGS(0, 0, aB, bB);
        LOAD_FRAGS(1, 1, aB, bB);
        MMA_BLOCK(0);                      // k 0-15
        LOAD_FRAGS(2, 0, aB, bB);
        MMA_BLOCK(1);                      // k 16-31
        LOAD_FRAGS(3, 1, aB, bB);
        MBARRIER_ARRIVE(EMPTY_BAR(slot));  // stage reads done — release early
        MMA_BLOCK(0);                      // k 32-47
        MMA_BLOCK(1);                      // k 48-63

        if (++slot == STAGES) { slot = 0; phase ^= 1; }
    }

    // ---- epilogue: fused bias ----
    const int gid = lane >> 2;
    const int kc = lane & 3;
    #pragma unroll
    for (int j = 0; j < 8; ++j) {
        const int col = n0 + wn0 + j * 8 + kc * 2;
        float2 bv;
        bv.x = __ldg(&g_B[col]);
        bv.y = __ldg(&g_B[col + 1]);
        #pragma unroll
        for (int i = 0; i < 4; ++i) {
            const int row = m0 + wm0 + i * 16 + gid;
            float2 v0 = make_float2(acc[i][j][0] + bv.x, acc[i][j][1] + bv.y);
            float2 v1 = make_float2(acc[i][j][2] + bv.x, acc[i][j][3] + bv.y);
            *reinterpret_cast<float2*>(out + (size_t)row * ODIM + col) = v0;
            *reinterpret_cast<float2*>(out + (size_t)(row + 8) * ODIM + col) = v1;
        }
    }
}

// ---------------------------------------------------------------------------
extern "C" void kernel_launch(void* const* d_in, const int* in_sizes, int n_in,
                              void* d_out, int out_size) {
    const float* x    = (const float*)d_in[0];
    const float* muw  = (const float*)d_in[1];
    const float* lsw  = (const float*)d_in[2];
    const float* mub  = (const float*)d_in[3];
    const float* lsb  = (const float*)d_in[4];
    const float* epsw = (const float*)d_in[5];
    const float* epsb = (const float*)d_in[6];
    float* out = (float*)d_out;

    cudaFuncSetAttribute(rand_linear_gemm_kernel,
                         cudaFuncAttributeMaxDynamicSharedMemorySize, SMEM_TOTAL);

    prep_all_kernel<<<PREP_BLOCKS, 256>>>((const float4*)muw, (const float4*)lsw,
                                          (const float4*)epsw, mub, lsb, epsb);

    rand_linear_gemm_kernel<<<(NROWS / TILE_M) * (ODIM / TILE_N), 320,
                              SMEM_TOTAL>>>(x, out);
}

// round 16
// speedup vs baseline: 1.2707x; 1.2707x over previous
#include <cuda_runtime.h>
#include <cuda_fp16.h>
#include <cstdint>
#include <cstddef>

// ---------------------------------------------------------------------------
// out[8192,4096] = x[8192,4096] @ W^T + b,  W = mu + exp(log_sigma)*eps
// R16 = R12 (best: fp16 m16n8k16, 256x128 CTA, 4-stage cp.async ring, fused
// prep) with ONE change: 4 producer warps (one per SMSP) instead of 2, for
// symmetric consumer/producer SMSP placement. Consumer loop R12-verbatim.
// ---------------------------------------------------------------------------
#define NROWS 8192
#define KDIM  4096
#define ODIM  4096

#define TILE_M 256
#define TILE_N 128
#define TILE_K 64                          // fp16: 64 halfs = 128 B/row
#define STAGES 4
#define K_ITERS (KDIM / TILE_K)            // 64

#define A_BYTES (TILE_M * TILE_K * 2)      // 32768
#define B_BYTES (TILE_N * TILE_K * 2)      // 16384
#define STAGE_BYTES (A_BYTES + B_BYTES)    // 49152
#define OFF_BAR   (STAGES * STAGE_BYTES)   // 196608
#define SMEM_TOTAL (OFF_BAR + 128)

__device__ __half g_X[(size_t)NROWS * KDIM];
__device__ __half g_W[(size_t)ODIM * KDIM];
__device__ float  g_B[ODIM];

// ---------------------------------------------------------------------------
__device__ __forceinline__ uint32_t smem_u32(const void* p) {
    uint32_t a;
    asm("{ .reg .u64 t; cvta.to.shared.u64 t, %1; cvt.u32.u64 %0, t; }"
        : "=r"(a) : "l"(p));
    return a;
}
__device__ __forceinline__ void cp16(uint32_t smem_dst, const void* gptr) {
    asm volatile("cp.async.cg.shared.global [%0], [%1], 16;"
                 :: "r"(smem_dst), "l"(gptr) : "memory");
}
__device__ __forceinline__ void cp_async_arrive(uint32_t mbar) {
    asm volatile("cp.async.mbarrier.arrive.noinc.shared.b64 [%0];"
                 :: "r"(mbar) : "memory");
}
#define MBARRIER_INIT(addr, cnt) \
    asm volatile("mbarrier.init.shared.b64 [%0], %1;" :: "r"(addr), "r"(cnt) : "memory")
#define MBARRIER_ARRIVE(addr) \
    asm volatile("mbarrier.arrive.shared.b64 _, [%0];" :: "r"(addr) : "memory")

__device__ __forceinline__ void mbar_wait(uint32_t mbar, uint32_t parity) {
    uint32_t done;
    asm volatile(
        "{ .reg .pred p; mbarrier.try_wait.parity.acquire.cta.shared::cta.b64 p, [%1], %2;"
        " selp.b32 %0, 1, 0, p; }"
        : "=r"(done) : "r"(mbar), "r"(parity) : "memory");
    if (!done) {
        asm volatile(
            "{ .reg .pred P1;\n"
            "WAIT_LOOP_%=:\n"
            " mbarrier.try_wait.parity.acquire.cta.shared::cta.b64 P1, [%0], %1, 0x989680;\n"
            " @P1 bra.uni WAIT_DONE_%=;\n"
            " bra.uni WAIT_LOOP_%=;\n"
            "WAIT_DONE_%=:\n}"
            :: "r"(mbar), "r"(parity) : "memory");
    }
}

__device__ __forceinline__ void ldsm_x4(uint32_t* r, uint32_t addr) {
    asm volatile("ldmatrix.sync.aligned.m8n8.x4.shared.b16 {%0,%1,%2,%3}, [%4];"
                 : "=r"(r[0]), "=r"(r[1]), "=r"(r[2]), "=r"(r[3]) : "r"(addr));
}
__device__ __forceinline__ void mma_f16(float* c, const uint32_t* a,
                                        uint32_t b0, uint32_t b1) {
    asm("mma.sync.aligned.m16n8k16.row.col.f32.f16.f16.f32 "
        "{%0,%1,%2,%3}, {%4,%5,%6,%7}, {%8,%9}, {%0,%1,%2,%3};"
        : "+f"(c[0]), "+f"(c[1]), "+f"(c[2]), "+f"(c[3])
        : "r"(a[0]), "r"(a[1]), "r"(a[2]), "r"(a[3]), "r"(b0), "r"(b1));
}

// ---------------------------------------------------------------------------
// Fused prep: blocks [0, 16384) convert x; [16384, 24576) sample+convert W;
// block 24576 samples bias.
// ---------------------------------------------------------------------------
#define PREP_X_BLOCKS 16384
#define PREP_W_BLOCKS 8192
#define PREP_BLOCKS (PREP_X_BLOCKS + PREP_W_BLOCKS + 1)

__global__ void prep_all_kernel(const float4* __restrict__ x,
                                const float4* __restrict__ mu,
                                const float4* __restrict__ ls,
                                const float4* __restrict__ eps,
                                const float* __restrict__ mub,
                                const float* __restrict__ lsb,
                                const float* __restrict__ epsb) {
    const int b = blockIdx.x;
    if (b < PREP_X_BLOCKS) {
        size_t i = (size_t)b * blockDim.x + threadIdx.x;
        float4 v0 = x[2 * i], v1 = x[2 * i + 1];
        __half2 h[4];
        h[0] = __floats2half2_rn(v0.x, v0.y);
        h[1] = __floats2half2_rn(v0.z, v0.w);
        h[2] = __floats2half2_rn(v1.x, v1.y);
        h[3] = __floats2half2_rn(v1.z, v1.w);
        reinterpret_cast<uint4*>(g_X)[i] = *reinterpret_cast<uint4*>(h);
    } else if (b < PREP_X_BLOCKS + PREP_W_BLOCKS) {
        size_t i = (size_t)(b - PREP_X_BLOCKS) * blockDim.x + threadIdx.x;
        __half2 h[4];
        #pragma unroll
        for (int q = 0; q < 2; ++q) {
            float4 m = mu[2 * i + q], l = ls[2 * i + q], e = eps[2 * i + q];
            float4 w;
            w.x = m.x + expf(l.x) * e.x;
            w.y = m.y + expf(l.y) * e.y;
            w.z = m.z + expf(l.z) * e.z;
            w.w = m.w + expf(l.w) * e.w;
            h[2 * q + 0] = __floats2half2_rn(w.x, w.y);
            h[2 * q + 1] = __floats2half2_rn(w.z, w.w);
        }
        reinterpret_cast<uint4*>(g_W)[i] = *reinterpret_cast<uint4*>(h);
    } else {
        for (int i = threadIdx.x; i < ODIM; i += blockDim.x)
            g_B[i] = mub[i] + expf(lsb[i]) * epsb[i];
    }
}

// ---------------------------------------------------------------------------
// GEMM: 1024 CTAs (32 m x 32 n, n fastest), 384 threads:
// warps 0-7 consumers (64x64 in 4x2), warps 8-11 producers (one per SMSP),
// each filling 1/4 of A (64 rows) and 1/4 of B (32 rows).
// full[s]: 128 cp-arrivals (4 warps); empty[s]: 256 consumer arrivals.
// ---------------------------------------------------------------------------
__global__ void __launch_bounds__(384, 1)
rand_linear_gemm_kernel(float* __restrict__ out) {
    extern __shared__ char smem[];
    const uint32_t sb = smem_u32(smem);
    const int tid = threadIdx.x;
    const int lane = tid & 31;
    const int wid = tid >> 5;

    const int m_tile = blockIdx.x >> 5;    // 32
    const int n_tile = blockIdx.x & 31;    // 32 (fast-varying: W stays L2-hot)
    const int m0 = m_tile * TILE_M;
    const int n0 = n_tile * TILE_N;

    #define FULL_BAR(s)  (sb + OFF_BAR + (s) * 16)
    #define EMPTY_BAR(s) (sb + OFF_BAR + (s) * 16 + 8)

    if (tid == 0) {
        #pragma unroll
        for (int s = 0; s < STAGES; ++s) {
            MBARRIER_INIT(FULL_BAR(s), 128u);   // 4 producer warps x 32 lanes
            MBARRIER_INIT(EMPTY_BAR(s), 256u);  // 8 consumer warps x 32 lanes
        }
    }
    __syncthreads();

    if (wid >= 8) {
        // ---- producer warps (one per SMSP): quarter of A + quarter of B ----
        const int ph = wid - 8;            // 0..3
        const int r0 = lane >> 3;          // 0..3
        const int tc = lane & 7;           // 16B chunk (8 halfs) in 128B row
        const __half* gA = g_X + (size_t)(m0 + ph * 64 + r0) * KDIM + tc * 8;
        const __half* gB = g_W + (size_t)(n0 + ph * 32 + r0) * KDIM + tc * 8;
        const uint32_t aOff = (uint32_t)(ph * 64) * 128u;
        const uint32_t bOff = (uint32_t)(ph * 32) * 128u;
        const uint32_t sw0 = (uint32_t)r0 * 128u + (uint32_t)((tc ^ (r0 & 7)) << 4);
        const uint32_t sw1 = (uint32_t)(r0 + 4) * 128u +
                             (uint32_t)((tc ^ ((r0 + 4) & 7)) << 4);

        int slot = 0, phase = 1;
        for (int it = 0; it < K_ITERS; ++it) {
            mbar_wait(EMPTY_BAR(slot), phase);
            const uint32_t aS = sb + slot * STAGE_BYTES + aOff;
            const uint32_t bS = sb + slot * STAGE_BYTES + A_BYTES + bOff;
            const __half* ga = gA + it * TILE_K;
            const __half* gb = gB + it * TILE_K;
            #pragma unroll
            for (int j = 0; j < 8; ++j) {    // A quarter: 64 rows
                cp16(aS + sw0 + j * 1024u, ga + (size_t)(8 * j) * KDIM);
                cp16(aS + sw1 + j * 1024u, ga + (size_t)(8 * j + 4) * KDIM);
            }
            #pragma unroll
            for (int j = 0; j < 4; ++j) {    // B quarter: 32 rows
                cp16(bS + sw0 + j * 1024u, gb + (size_t)(8 * j) * KDIM);
                cp16(bS + sw1 + j * 1024u, gb + (size_t)(8 * j + 4) * KDIM);
            }
            cp_async_arrive(FULL_BAR(slot));
            if (++slot == STAGES) { slot = 0; phase ^= 1; }
        }
        return;
    }

    // --------------------------- consumer warps (R12 verbatim) -------------
    const int wm0 = (wid & 3) * 64;
    const int wn0 = (wid >> 2) * 64;

    const int la15 = lane & 15;
    const uint32_t hi = (uint32_t)(lane >> 4);
    uint32_t aRow[4], aX7[4], bRow[4], bX7[4];
    #pragma unroll
    for (int i = 0; i < 4; ++i) {
        const uint32_t ra = (uint32_t)(wm0 + i * 16 + la15);
        aRow[i] = ra * 128u; aX7[i] = ra & 7u;
        const uint32_t rb = (uint32_t)(wn0 + i * 16 + la15);
        bRow[i] = rb * 128u; bX7[i] = rb & 7u;
    }

    float acc[4][8][4];
    #pragma unroll
    for (int i = 0; i < 4; ++i)
        #pragma unroll
        for (int j = 0; j < 8; ++j)
            #pragma unroll
            for (int r = 0; r < 4; ++r) acc[i][j][r] = 0.f;

    uint32_t a[2][4][4], b[2][4][4];

    #define LOAD_FRAGS(kk, buf, aB_, bB_)                                     \
        do {                                                                  \
            const uint32_t kc2 = (uint32_t)((kk) * 2) + hi;                   \
            _Pragma("unroll")                                                 \
            for (int i_ = 0; i_ < 4; ++i_)                                    \
                ldsm_x4(a[buf][i_], (aB_) + aRow[i_] + ((kc2 ^ aX7[i_]) << 4)); \
            _Pragma("unroll")                                                 \
            for (int j_ = 0; j_ < 4; ++j_)                                    \
                ldsm_x4(b[buf][j_], (bB_) + bRow[j_] + ((kc2 ^ bX7[j_]) << 4)); \
        } while (0)

    #define MMA_BLOCK(buf)                                                    \
        do {                                                                  \
            _Pragma("unroll")                                                 \
            for (int i_ = 0; i_ < 4; ++i_) {                                  \
                _Pragma("unroll")                                             \
                for (int j_ = 0; j_ < 4; ++j_) {                              \
                    mma_f16(acc[i_][2 * j_ + 0], a[buf][i_], b[buf][j_][0],   \
                            b[buf][j_][2]);                                   \
                    mma_f16(acc[i_][2 * j_ + 1], a[buf][i_], b[buf][j_][1],   \
                            b[buf][j_][3]);                                   \
                }                                                             \
            }                                                                 \
        } while (0)

    int slot = 0, phase = 0;
    for (int it = 0; it < K_ITERS; ++it) {
        mbar_wait(FULL_BAR(slot), phase);
        const uint32_t aB = sb + slot * STAGE_BYTES;
        const uint32_t bB = aB + A_BYTES;

        LOAD_FRAGS(0, 0, aB, bB);
        LOAD_FRAGS(1, 1, aB, bB);
        MMA_BLOCK(0);                      // k 0-15
        LOAD_FRAGS(2, 0, aB, bB);
        MMA_BLOCK(1);                      // k 16-31
        LOAD_FRAGS(3, 1, aB, bB);
        MBARRIER_ARRIVE(EMPTY_BAR(slot));  // stage reads done — release early
        MMA_BLOCK(0);                      // k 32-47
        MMA_BLOCK(1);                      // k 48-63

        if (++slot == STAGES) { slot = 0; phase ^= 1; }
    }

    // ---- epilogue: fused bias ----
    const int gid = lane >> 2;
    const int kc = lane & 3;
    #pragma unroll
    for (int j = 0; j < 8; ++j) {
        const int col = n0 + wn0 + j * 8 + kc * 2;
        float2 bv;
        bv.x = __ldg(&g_B[col]);
        bv.y = __ldg(&g_B[col + 1]);
        #pragma unroll
        for (int i = 0; i < 4; ++i) {
            const int row = m0 + wm0 + i * 16 + gid;
            float2 v0 = make_float2(acc[i][j][0] + bv.x, acc[i][j][1] + bv.y);
            float2 v1 = make_float2(acc[i][j][2] + bv.x, acc[i][j][3] + bv.y);
            *reinterpret_cast<float2*>(out + (size_t)row * ODIM + col) = v0;
            *reinterpret_cast<float2*>(out + (size_t)(row + 8) * ODIM + col) = v1;
        }
    }
}

// ---------------------------------------------------------------------------
extern "C" void kernel_launch(void* const* d_in, const int* in_sizes, int n_in,
                              void* d_out, int out_size) {
    const float* x    = (const float*)d_in[0];
    const float* muw  = (const float*)d_in[1];
    const float* lsw  = (const float*)d_in[2];
    const float* mub  = (const float*)d_in[3];
    const float* lsb  = (const float*)d_in[4];
    const float* epsw = (const float*)d_in[5];
    const float* epsb = (const float*)d_in[6];
    float* out = (float*)d_out;

    cudaFuncSetAttribute(rand_linear_gemm_kernel,
                         cudaFuncAttributeMaxDynamicSharedMemorySize, SMEM_TOTAL);

    prep_all_kernel<<<PREP_BLOCKS, 256>>>((const float4*)x, (const float4*)muw,
                                          (const float4*)lsw, (const float4*)epsw,
                                          mub, lsb, epsb);

    rand_linear_gemm_kernel<<<(NROWS / TILE_M) * (ODIM / TILE_N), 384,
                              SMEM_TOTAL>>>(out);
}

// round 17
// speedup vs baseline: 1.2852x; 1.0114x over previous
#include <cuda_runtime.h>
#include <cuda_fp16.h>
#include <cstdint>
#include <cstddef>

// ---------------------------------------------------------------------------
// out[8192,4096] = x[8192,4096] @ W^T + b,  W = mu + exp(log_sigma)*eps
// R17 = R12 (session best, 712.2us) locked in: fp16 m16n8k16 mma.sync,
// CTA 256x128, 8 consumer warps (64x64) + 2 producer warps, 4-stage
// cp.async + mbarrier ring, fused prep (512-thread blocks).
// GEMM wall established: mma.sync effective rt ~11 cyc/SMSP on sm_103a;
// tcgen05 unreachable (harness PTX target = compute_103, no .a features).
// ---------------------------------------------------------------------------
#define NROWS 8192
#define KDIM  4096
#define ODIM  4096

#define TILE_M 256
#define TILE_N 128
#define TILE_K 64                          // fp16: 64 halfs = 128 B/row
#define STAGES 4
#define K_ITERS (KDIM / TILE_K)            // 64

#define A_BYTES (TILE_M * TILE_K * 2)      // 32768
#define B_BYTES (TILE_N * TILE_K * 2)      // 16384
#define STAGE_BYTES (A_BYTES + B_BYTES)    // 49152
#define OFF_BAR   (STAGES * STAGE_BYTES)   // 196608
#define SMEM_TOTAL (OFF_BAR + 128)

__device__ __half g_X[(size_t)NROWS * KDIM];
__device__ __half g_W[(size_t)ODIM * KDIM];
__device__ float  g_B[ODIM];

// ---------------------------------------------------------------------------
__device__ __forceinline__ uint32_t smem_u32(const void* p) {
    uint32_t a;
    asm("{ .reg .u64 t; cvta.to.shared.u64 t, %1; cvt.u32.u64 %0, t; }"
        : "=r"(a) : "l"(p));
    return a;
}
__device__ __forceinline__ void cp16(uint32_t smem_dst, const void* gptr) {
    asm volatile("cp.async.cg.shared.global [%0], [%1], 16;"
                 :: "r"(smem_dst), "l"(gptr) : "memory");
}
__device__ __forceinline__ void cp_async_arrive(uint32_t mbar) {
    asm volatile("cp.async.mbarrier.arrive.noinc.shared.b64 [%0];"
                 :: "r"(mbar) : "memory");
}
#define MBARRIER_INIT(addr, cnt) \
    asm volatile("mbarrier.init.shared.b64 [%0], %1;" :: "r"(addr), "r"(cnt) : "memory")
#define MBARRIER_ARRIVE(addr) \
    asm volatile("mbarrier.arrive.shared.b64 _, [%0];" :: "r"(addr) : "memory")

__device__ __forceinline__ void mbar_wait(uint32_t mbar, uint32_t parity) {
    uint32_t done;
    asm volatile(
        "{ .reg .pred p; mbarrier.try_wait.parity.acquire.cta.shared::cta.b64 p, [%1], %2;"
        " selp.b32 %0, 1, 0, p; }"
        : "=r"(done) : "r"(mbar), "r"(parity) : "memory");
    if (!done) {
        asm volatile(
            "{ .reg .pred P1;\n"
            "WAIT_LOOP_%=:\n"
            " mbarrier.try_wait.parity.acquire.cta.shared::cta.b64 P1, [%0], %1, 0x989680;\n"
            " @P1 bra.uni WAIT_DONE_%=;\n"
            " bra.uni WAIT_LOOP_%=;\n"
            "WAIT_DONE_%=:\n}"
            :: "r"(mbar), "r"(parity) : "memory");
    }
}

__device__ __forceinline__ void ldsm_x4(uint32_t* r, uint32_t addr) {
    asm volatile("ldmatrix.sync.aligned.m8n8.x4.shared.b16 {%0,%1,%2,%3}, [%4];"
                 : "=r"(r[0]), "=r"(r[1]), "=r"(r[2]), "=r"(r[3]) : "r"(addr));
}
__device__ __forceinline__ void mma_f16(float* c, const uint32_t* a,
                                        uint32_t b0, uint32_t b1) {
    asm volatile(
        "mma.sync.aligned.m16n8k16.row.col.f32.f16.f16.f32 "
        "{%0,%1,%2,%3}, {%4,%5,%6,%7}, {%8,%9}, {%0,%1,%2,%3};"
        : "+f"(c[0]), "+f"(c[1]), "+f"(c[2]), "+f"(c[3])
        : "r"(a[0]), "r"(a[1]), "r"(a[2]), "r"(a[3]), "r"(b0), "r"(b1));
}

// ---------------------------------------------------------------------------
// Fused prep (512-thread blocks): [0, 8192) convert x; [8192, 12288) sample
// + convert W; block 12288 samples bias. Each thread: 8 elements.
// ---------------------------------------------------------------------------
#define PREP_X_BLOCKS 8192
#define PREP_W_BLOCKS 4096
#define PREP_BLOCKS (PREP_X_BLOCKS + PREP_W_BLOCKS + 1)

__global__ void __launch_bounds__(512)
prep_all_kernel(const float4* __restrict__ x,
                const float4* __restrict__ mu,
                const float4* __restrict__ ls,
                const float4* __restrict__ eps,
                const float* __restrict__ mub,
                const float* __restrict__ lsb,
                const float* __restrict__ epsb) {
    const int b = blockIdx.x;
    if (b < PREP_X_BLOCKS) {
        size_t i = (size_t)b * blockDim.x + threadIdx.x;
        float4 v0 = x[2 * i], v1 = x[2 * i + 1];
        __half2 h[4];
        h[0] = __floats2half2_rn(v0.x, v0.y);
        h[1] = __floats2half2_rn(v0.z, v0.w);
        h[2] = __floats2half2_rn(v1.x, v1.y);
        h[3] = __floats2half2_rn(v1.z, v1.w);
        reinterpret_cast<uint4*>(g_X)[i] = *reinterpret_cast<uint4*>(h);
    } else if (b < PREP_X_BLOCKS + PREP_W_BLOCKS) {
        size_t i = (size_t)(b - PREP_X_BLOCKS) * blockDim.x + threadIdx.x;
        __half2 h[4];
        #pragma unroll
        for (int q = 0; q < 2; ++q) {
            float4 m = mu[2 * i + q], l = ls[2 * i + q], e = eps[2 * i + q];
            float4 w;
            w.x = m.x + expf(l.x) * e.x;
            w.y = m.y + expf(l.y) * e.y;
            w.z = m.z + expf(l.z) * e.z;
            w.w = m.w + expf(l.w) * e.w;
            h[2 * q + 0] = __floats2half2_rn(w.x, w.y);
            h[2 * q + 1] = __floats2half2_rn(w.z, w.w);
        }
        reinterpret_cast<uint4*>(g_W)[i] = *reinterpret_cast<uint4*>(h);
    } else {
        for (int i = threadIdx.x; i < ODIM; i += blockDim.x)
            g_B[i] = mub[i] + expf(lsb[i]) * epsb[i];
    }
}

// ---------------------------------------------------------------------------
// GEMM: 1024 CTAs (32 m x 32 n, n fastest), 320 threads:
// warps 0-7 consumers (64x64 in 4x2), warps 8-9 producers (A/B halves).
// full[s]: 64 cp-arrivals; empty[s]: 256 consumer arrivals.
// ---------------------------------------------------------------------------
__global__ void __launch_bounds__(320, 1)
rand_linear_gemm_kernel(float* __restrict__ out) {
    extern __shared__ char smem[];
    const uint32_t sb = smem_u32(smem);
    const int tid = threadIdx.x;
    const int lane = tid & 31;
    const int wid = tid >> 5;

    const int m_tile = blockIdx.x >> 5;    // 32
    const int n_tile = blockIdx.x & 31;    // 32 (fast-varying: W stays L2-hot)
    const int m0 = m_tile * TILE_M;
    const int n0 = n_tile * TILE_N;

    #define FULL_BAR(s)  (sb + OFF_BAR + (s) * 16)
    #define EMPTY_BAR(s) (sb + OFF_BAR + (s) * 16 + 8)

    if (tid == 0) {
        #pragma unroll
        for (int s = 0; s < STAGES; ++s) {
            MBARRIER_INIT(FULL_BAR(s), 64u);    // 2 producer warps x 32 lanes
            MBARRIER_INIT(EMPTY_BAR(s), 256u);  // 8 consumer warps x 32 lanes
        }
    }
    __syncthreads();

    if (wid >= 8) {
        const int ph = wid - 8;            // 0 or 1
        const int r0 = lane >> 3;          // 0..3
        const int tc = lane & 7;           // 16B chunk (8 halfs) in 128B row
        const __half* gA = g_X + (size_t)(m0 + ph * 128 + r0) * KDIM + tc * 8;
        const __half* gB = g_W + (size_t)(n0 + ph * 64 + r0) * KDIM + tc * 8;
        const uint32_t aOff = (uint32_t)(ph * 128) * 128u;
        const uint32_t bOff = (uint32_t)(ph * 64) * 128u;
        const uint32_t sw0 = (uint32_t)r0 * 128u + (uint32_t)((tc ^ (r0 & 7)) << 4);
        const uint32_t sw1 = (uint32_t)(r0 + 4) * 128u +
                             (uint32_t)((tc ^ ((r0 + 4) & 7)) << 4);

        int slot = 0, phase = 1;
        for (int it = 0; it < K_ITERS; ++it) {
            mbar_wait(EMPTY_BAR(slot), phase);
            const uint32_t aS = sb + slot * STAGE_BYTES + aOff;
            const uint32_t bS = sb + slot * STAGE_BYTES + A_BYTES + bOff;
            const __half* ga = gA + it * TILE_K;
            const __half* gb = gB + it * TILE_K;
            #pragma unroll
            for (int j = 0; j < 16; ++j) {   // A half: 128 rows
                cp16(aS + sw0 + j * 1024u, ga + (size_t)(8 * j) * KDIM);
                cp16(aS + sw1 + j * 1024u, ga + (size_t)(8 * j + 4) * KDIM);
            }
            #pragma unroll
            for (int j = 0; j < 8; ++j) {    // B half: 64 rows
                cp16(bS + sw0 + j * 1024u, gb + (size_t)(8 * j) * KDIM);
                cp16(bS + sw1 + j * 1024u, gb + (size_t)(8 * j + 4) * KDIM);
            }
            cp_async_arrive(FULL_BAR(slot));
            if (++slot == STAGES) { slot = 0; phase ^= 1; }
        }
        return;
    }

    // --------------------------- consumer warps ---------------------------
    const int wm0 = (wid & 3) * 64;
    const int wn0 = (wid >> 2) * 64;

    const int la15 = lane & 15;
    const uint32_t hi = (uint32_t)(lane >> 4);
    uint32_t aRow[4], aX7[4], bRow[4], bX7[4];
    #pragma unroll
    for (int i = 0; i < 4; ++i) {
        const uint32_t ra = (uint32_t)(wm0 + i * 16 + la15);
        aRow[i] = ra * 128u; aX7[i] = ra & 7u;
        const uint32_t rb = (uint32_t)(wn0 + i * 16 + la15);
        bRow[i] = rb * 128u; bX7[i] = rb & 7u;
    }

    float acc[4][8][4];
    #pragma unroll
    for (int i = 0; i < 4; ++i)
        #pragma unroll
        for (int j = 0; j < 8; ++j)
            #pragma unroll
            for (int r = 0; r < 4; ++r) acc[i][j][r] = 0.f;

    uint32_t a[2][4][4], b[2][4][4];

    #define LOAD_FRAGS(kk, buf, aB_, bB_)                                     \
        do {                                                                  \
            const uint32_t kc2 = (uint32_t)((kk) * 2) + hi;                   \
            _Pragma("unroll")                                                 \
            for (int i_ = 0; i_ < 4; ++i_)                                    \
                ldsm_x4(a[buf][i_], (aB_) + aRow[i_] + ((kc2 ^ aX7[i_]) << 4)); \
            _Pragma("unroll")                                                 \
            for (int j_ = 0; j_ < 4; ++j_)                                    \
                ldsm_x4(b[buf][j_], (bB_) + bRow[j_] + ((kc2 ^ bX7[j_]) << 4)); \
        } while (0)

    #define MMA_BLOCK(buf)                                                    \
        do {                                                                  \
            _Pragma("unroll")                                                 \
            for (int i_ = 0; i_ < 4; ++i_) {                                  \
                _Pragma("unroll")                                             \
                for (int j_ = 0; j_ < 4; ++j_) {                              \
                    mma_f16(acc[i_][2 * j_ + 0], a[buf][i_], b[buf][j_][0],   \
                            b[buf][j_][2]);                                   \
                    mma_f16(acc[i_][2 * j_ + 1], a[buf][i_], b[buf][j_][1],   \
                            b[buf][j_][3]);                                   \
                }                                                             \
            }                                                                 \
        } while (0)

    int slot = 0, phase = 0;
    for (int it = 0; it < K_ITERS; ++it) {
        mbar_wait(FULL_BAR(slot), phase);
        const uint32_t aB = sb + slot * STAGE_BYTES;
        const uint32_t bB = aB + A_BYTES;

        LOAD_FRAGS(0, 0, aB, bB);
        LOAD_FRAGS(1, 1, aB, bB);
        MMA_BLOCK(0);                      // k 0-15
        LOAD_FRAGS(2, 0, aB, bB);
        MMA_BLOCK(1);                      // k 16-31
        LOAD_FRAGS(3, 1, aB, bB);
        MBARRIER_ARRIVE(EMPTY_BAR(slot));  // stage reads done — release early
        MMA_BLOCK(0);                      // k 32-47
        MMA_BLOCK(1);                      // k 48-63

        if (++slot == STAGES) { slot = 0; phase ^= 1; }
    }

    // ---- epilogue: fused bias ----
    const int gid = lane >> 2;
    const int kc = lane & 3;
    #pragma unroll
    for (int j = 0; j < 8; ++j) {
        const int col = n0 + wn0 + j * 8 + kc * 2;
        float2 bv;
        bv.x = __ldg(&g_B[col]);
        bv.y = __ldg(&g_B[col + 1]);
        #pragma unroll
        for (int i = 0; i < 4; ++i) {
            const int row = m0 + wm0 + i * 16 + gid;
            float2 v0 = make_float2(acc[i][j][0] + bv.x, acc[i][j][1] + bv.y);
            float2 v1 = make_float2(acc[i][j][2] + bv.x, acc[i][j][3] + bv.y);
            *reinterpret_cast<float2*>(out + (size_t)row * ODIM + col) = v0;
            *reinterpret_cast<float2*>(out + (size_t)(row + 8) * ODIM + col) = v1;
        }
    }
}

// ---------------------------------------------------------------------------
extern "C" void kernel_launch(void* const* d_in, const int* in_sizes, int n_in,
                              void* d_out, int out_size) {
    const float* x    = (const float*)d_in[0];
    const float* muw  = (const float*)d_in[1];
    const float* lsw  = (const float*)d_in[2];
    const float* mub  = (const float*)d_in[3];
    const float* lsb  = (const float*)d_in[4];
    const float* epsw = (const float*)d_in[5];
    const float* epsb = (const float*)d_in[6];
    float* out = (float*)d_out;

    cudaFuncSetAttribute(rand_linear_gemm_kernel,
                         cudaFuncAttributeMaxDynamicSharedMemorySize, SMEM_TOTAL);

    prep_all_kernel<<<PREP_BLOCKS, 512>>>((const float4*)x, (const float4*)muw,
                                          (const float4*)lsw, (const float4*)epsw,
                                          mub, lsb, epsb);

    rand_linear_gemm_kernel<<<(NROWS / TILE_M) * (ODIM / TILE_N), 320,
                              SMEM_TOTAL>>>(out);
}